// round 6
// baseline (speedup 1.0000x reference)
#include <cuda_runtime.h>

#define BB 8
#define CC 256
#define NNS 16384
#define BN_EPS 1e-5f
#define SPLITS 16

// ---------------- scratch (static device globals; no allocation allowed) ----------------
__device__ __align__(16) float g_k[(size_t)BB * CC * NNS];              // 134 MB: K = Wk @ X
__device__ __align__(16) float g_m[BB * CC];                            // per-row max
__device__ __align__(16) float g_s[BB * CC];                            // per-row 1/sum(exp)
__device__ __align__(16) float g_Spp[(size_t)SPLITS * BB * CC * CC];    // 134 MB: split-K partials
__device__ __align__(16) float g_Sp[BB * CC * CC];                      // S' = exp(K-m) @ X^T
__device__ __align__(16) float g_A0[CC * CC];                           // Wproj @ Wv
__device__ __align__(16) float g_U[BB * CC * CC];                       // Snorm^T @ Wq (weighted)
__device__ __align__(16) float g_P2[BB * CC * CC];                      // diag(inv) * A0 @ U

// packed dual fp32 FMA (FFMA2) — only reachable via PTX fma.rn.f32x2
__device__ __forceinline__ void fma2(float2& acc, float2 a, float2 b) {
    asm("fma.rn.f32x2 %0, %1, %2, %0;"
        : "+l"(*reinterpret_cast<unsigned long long*>(&acc))
        : "l"(*reinterpret_cast<const unsigned long long*>(&a)),
          "l"(*reinterpret_cast<const unsigned long long*>(&b)));
}

// ---------------- big GEMM: C[b] (256 x 16384) = A[b] (256x256) @ X[b] (256x16384) ----------------
// SRC_P2==0: A = Aparam (shared across batch). SRC_P2==1: A = g_P2 + b*CC*CC.
// DST_K==1: C = g_k (internal scratch). DST_K==0: C = Cm param (harness output).
// EPI==1: fused BN bias + ReLU (inv already folded into P2 rows).
template <int SRC_P2, int DST_K, int EPI>
__global__ void __launch_bounds__(256, 2)
gemm_big(const float* __restrict__ Aparam,
         const float* __restrict__ Bm, float* __restrict__ Cm,
         const float* __restrict__ gamma, const float* __restrict__ beta,
         const float* __restrict__ rmean, const float* __restrict__ rvar)
{
    const int b = blockIdx.z;
    const float* Ab = SRC_P2 ? (g_P2 + (long)b * CC * CC) : Aparam;
    const float* Bb = Bm + (long)b * CC * NNS;
    float* Cb = (DST_K ? g_k : Cm) + (long)b * CC * NNS;
    const int m0 = blockIdx.y * 128;
    const int n0 = blockIdx.x * 128;

    __shared__ __align__(16) float As[16][132];  // [k][m] transposed, padded
    __shared__ __align__(16) float Bs[16][128];  // [k][n]

    const int tid = threadIdx.x;
    const int tx = tid & 15, ty = tid >> 4;

    float2 acc[8][4];
#pragma unroll
    for (int i = 0; i < 8; ++i)
#pragma unroll
        for (int j = 0; j < 4; ++j) acc[i][j] = make_float2(0.f, 0.f);

    for (int k0 = 0; k0 < CC; k0 += 16) {
#pragma unroll
        for (int p = 0; p < 2; ++p) {
            int idx = tid + p * 256;
            int ar = idx >> 2, ac = (idx & 3) << 2;
            float4 av = *reinterpret_cast<const float4*>(Ab + (long)(m0 + ar) * CC + k0 + ac);
            As[ac + 0][ar] = av.x; As[ac + 1][ar] = av.y;
            As[ac + 2][ar] = av.z; As[ac + 3][ar] = av.w;
            int br = idx >> 5, bc = (idx & 31) << 2;
            *reinterpret_cast<float4*>(&Bs[br][bc]) =
                *reinterpret_cast<const float4*>(Bb + (long)(k0 + br) * NNS + n0 + bc);
        }
        __syncthreads();
#pragma unroll
        for (int kk = 0; kk < 16; ++kk) {
            float4 a0 = *reinterpret_cast<const float4*>(&As[kk][ty * 8]);
            float4 a1 = *reinterpret_cast<const float4*>(&As[kk][ty * 8 + 4]);
            float4 b0 = *reinterpret_cast<const float4*>(&Bs[kk][tx * 8]);
            float4 b1 = *reinterpret_cast<const float4*>(&Bs[kk][tx * 8 + 4]);
            float2 bp[4] = {make_float2(b0.x, b0.y), make_float2(b0.z, b0.w),
                            make_float2(b1.x, b1.y), make_float2(b1.z, b1.w)};
            float aa[8] = {a0.x, a0.y, a0.z, a0.w, a1.x, a1.y, a1.z, a1.w};
#pragma unroll
            for (int i = 0; i < 8; ++i) {
                float2 av2 = make_float2(aa[i], aa[i]);
#pragma unroll
                for (int j = 0; j < 4; ++j) fma2(acc[i][j], av2, bp[j]);
            }
        }
        __syncthreads();
    }

    const int ng = n0 + tx * 8;
#pragma unroll
    for (int i = 0; i < 8; ++i) {
        int mg = m0 + ty * 8 + i;
        float r[8] = {acc[i][0].x, acc[i][0].y, acc[i][1].x, acc[i][1].y,
                      acc[i][2].x, acc[i][2].y, acc[i][3].x, acc[i][3].y};
        if (EPI == 1) {
            float inv = gamma[mg] * rsqrtf(rvar[mg] + BN_EPS);
            float bias = beta[mg] - rmean[mg] * inv;
#pragma unroll
            for (int j = 0; j < 8; ++j) r[j] = fmaxf(r[j] + bias, 0.f);
        }
        *reinterpret_cast<float4*>(Cb + (long)mg * NNS + ng)     = make_float4(r[0], r[1], r[2], r[3]);
        *reinterpret_cast<float4*>(Cb + (long)mg * NNS + ng + 4) = make_float4(r[4], r[5], r[6], r[7]);
    }
}

// ---------------- per-row max + 1/sum(exp) over N=16384, one gmem pass ----------------
__global__ void __launch_bounds__(256)
rowstats()
{
    const long row = blockIdx.x;  // 0..2047 == b*256 + o
    const float4* kr = reinterpret_cast<const float4*>(g_k) + row * (NNS / 4);
    const int t = threadIdx.x;

    float4 v[16];
    float mx = -3.402823466e38f;
#pragma unroll
    for (int i = 0; i < 16; ++i) {
        v[i] = kr[t + (i << 8)];
        mx = fmaxf(mx, fmaxf(fmaxf(v[i].x, v[i].y), fmaxf(v[i].z, v[i].w)));
    }
    __shared__ float red[8];
    __shared__ float bmax;
#pragma unroll
    for (int o = 16; o; o >>= 1) mx = fmaxf(mx, __shfl_xor_sync(0xffffffffu, mx, o));
    if ((t & 31) == 0) red[t >> 5] = mx;
    __syncthreads();
    if (t < 32) {
        float x = (t < 8) ? red[t] : -3.402823466e38f;
#pragma unroll
        for (int o = 4; o; o >>= 1) x = fmaxf(x, __shfl_xor_sync(0xffffffffu, x, o));
        if (t == 0) bmax = x;
    }
    __syncthreads();
    const float m = bmax;

    float s = 0.f;
#pragma unroll
    for (int i = 0; i < 16; ++i)
        s += __expf(v[i].x - m) + __expf(v[i].y - m) + __expf(v[i].z - m) + __expf(v[i].w - m);
#pragma unroll
    for (int o = 16; o; o >>= 1) s += __shfl_xor_sync(0xffffffffu, s, o);
    if ((t & 31) == 0) red[t >> 5] = s;
    __syncthreads();
    if (t < 32) {
        float x = (t < 8) ? red[t] : 0.f;
#pragma unroll
        for (int o = 4; o; o >>= 1) x += __shfl_xor_sync(0xffffffffu, x, o);
        if (t == 0) { g_m[row] = m; g_s[row] = 1.0f / x; }
    }
}

// ---------------- S'_partial[split][b] (256x256) = exp(K-m) @ X^T over its N-chunk ----------------
__global__ void __launch_bounds__(256, 2)
gemm_ctx(const float* __restrict__ x)
{
    const int zz = blockIdx.z;
    const int b = zz >> 4;
    const int split = zz & 15;
    const int o0 = blockIdx.y * 128;
    const int c0 = blockIdx.x * 128;
    const long nbase = (long)split * (NNS / SPLITS);   // chunks of 1024
    const float* kb = g_k + ((long)b * CC + o0) * NNS;
    const float* xb = x + ((long)b * CC + c0) * NNS;

    __shared__ __align__(16) float Es[16][132];  // [n][o]
    __shared__ __align__(16) float Xs[16][132];  // [n][c]
    __shared__ float ms[128];

    const int tid = threadIdx.x;
    if (tid < 128) ms[tid] = g_m[b * CC + o0 + tid];
    __syncthreads();

    const int tx = tid & 15, ty = tid >> 4;
    float2 acc[8][4];
#pragma unroll
    for (int i = 0; i < 8; ++i)
#pragma unroll
        for (int j = 0; j < 4; ++j) acc[i][j] = make_float2(0.f, 0.f);

    for (int kt = 0; kt < (NNS / SPLITS) / 16; ++kt) {   // 64 iterations
        const long nb = nbase + kt * 16;
#pragma unroll
        for (int p = 0; p < 2; ++p) {
            int idx = tid + p * 256;
            int r = idx >> 2, c4 = (idx & 3) << 2;
            float4 kv = *reinterpret_cast<const float4*>(kb + (long)r * NNS + nb + c4);
            float mr = ms[r];
            Es[c4 + 0][r] = __expf(kv.x - mr);
            Es[c4 + 1][r] = __expf(kv.y - mr);
            Es[c4 + 2][r] = __expf(kv.z - mr);
            Es[c4 + 3][r] = __expf(kv.w - mr);
            float4 xv = *reinterpret_cast<const float4*>(xb + (long)r * NNS + nb + c4);
            Xs[c4 + 0][r] = xv.x; Xs[c4 + 1][r] = xv.y;
            Xs[c4 + 2][r] = xv.z; Xs[c4 + 3][r] = xv.w;
        }
        __syncthreads();
#pragma unroll
        for (int kk = 0; kk < 16; ++kk) {
            float4 a0 = *reinterpret_cast<const float4*>(&Es[kk][ty * 8]);
            float4 a1 = *reinterpret_cast<const float4*>(&Es[kk][ty * 8 + 4]);
            float4 b0 = *reinterpret_cast<const float4*>(&Xs[kk][tx * 8]);
            float4 b1 = *reinterpret_cast<const float4*>(&Xs[kk][tx * 8 + 4]);
            float2 bp[4] = {make_float2(b0.x, b0.y), make_float2(b0.z, b0.w),
                            make_float2(b1.x, b1.y), make_float2(b1.z, b1.w)};
            float aa[8] = {a0.x, a0.y, a0.z, a0.w, a1.x, a1.y, a1.z, a1.w};
#pragma unroll
            for (int i = 0; i < 8; ++i) {
                float2 av2 = make_float2(aa[i], aa[i]);
#pragma unroll
                for (int j = 0; j < 4; ++j) fma2(acc[i][j], av2, bp[j]);
            }
        }
        __syncthreads();
    }

    // plain stores to this split's private partial buffer — no atomics, no pre-zeroing
    float* base = g_Spp + ((long)split * BB + b) * CC * CC;
#pragma unroll
    for (int i = 0; i < 8; ++i) {
        int og = o0 + ty * 8 + i;
        float* dst = base + (long)og * CC + c0 + tx * 8;
        *reinterpret_cast<float4*>(dst)     = make_float4(acc[i][0].x, acc[i][0].y, acc[i][1].x, acc[i][1].y);
        *reinterpret_cast<float4*>(dst + 4) = make_float4(acc[i][2].x, acc[i][2].y, acc[i][3].x, acc[i][3].y);
    }
}

// ---------------- reduce the 16 split partials into g_Sp ----------------
__global__ void __launch_bounds__(256)
reduce_sp()
{
    const int idx = blockIdx.x * 256 + threadIdx.x;   // 0..131071 float4s
    const float4* src = reinterpret_cast<const float4*>(g_Spp);
    float4 a = make_float4(0.f, 0.f, 0.f, 0.f);
#pragma unroll
    for (int s = 0; s < SPLITS; ++s) {
        float4 v = src[(long)s * (BB * CC * CC / 4) + idx];
        a.x += v.x; a.y += v.y; a.z += v.z; a.w += v.w;
    }
    reinterpret_cast<float4*>(g_Sp)[idx] = a;
}

// ---------------- small 256x256x256 GEMMs (per-batch chain for P2) ----------------
// MODE 0: g_A0 = in0(Wproj) @ in1(Wv)
// MODE 1: g_U[b][m][n] = sum_k g_s[b][k] * g_Sp[b][k][m] * in0(Wq)[k][n]
// MODE 2: g_P2[b] = diag(gamma*rsqrt(rvar+eps)) * (g_A0 @ g_U[b])
template <int MODE>
__global__ void __launch_bounds__(256)
sgemm_small(const float* __restrict__ in0, const float* __restrict__ in1,
            const float* __restrict__ gamma, const float* __restrict__ rvar)
{
    const int LD = CC;
    const int b = blockIdx.z;
    const float* A = (MODE == 0) ? in0 : (MODE == 1) ? (g_Sp + (long)b * CC * CC) : g_A0;
    const float* Bm = (MODE == 0) ? in1 : (MODE == 1) ? in0 : (g_U + (long)b * CC * CC);
    float* Cm = (MODE == 0) ? g_A0 : (MODE == 1) ? (g_U + (long)b * CC * CC)
                                                  : (g_P2 + (long)b * CC * CC);
    const float* ks = (MODE == 1) ? (g_s + (long)b * CC) : nullptr;
    const int m0 = blockIdx.y * 64, n0 = blockIdx.x * 64;

    __shared__ float As[16][65];
    __shared__ float Bs[16][65];

    const int tid = threadIdx.x;
    const int tx = tid & 15, ty = tid >> 4;
    float acc[4][4] = {};

    for (int k0 = 0; k0 < CC; k0 += 16) {
#pragma unroll
        for (int p = 0; p < 4; ++p) {
            int idx = tid + p * 256;     // 0..1023
            if (MODE == 1) {             // A accessed transposed: A[k][m], scaled by ks[k]
                int kk = idx >> 6, mm = idx & 63;
                As[kk][mm] = A[(long)(k0 + kk) * LD + m0 + mm] * ks[k0 + kk];
            } else {
                int mm = idx >> 4, kk = idx & 15;
                As[kk][mm] = A[(long)(m0 + mm) * LD + k0 + kk];
            }
            int kk2 = idx >> 6, nn2 = idx & 63;
            Bs[kk2][nn2] = Bm[(long)(k0 + kk2) * LD + n0 + nn2];
        }
        __syncthreads();
#pragma unroll
        for (int kk = 0; kk < 16; ++kk) {
            float a[4], bb[4];
#pragma unroll
            for (int i = 0; i < 4; ++i) { a[i] = As[kk][ty * 4 + i]; bb[i] = Bs[kk][tx * 4 + i]; }
#pragma unroll
            for (int i = 0; i < 4; ++i)
#pragma unroll
                for (int j = 0; j < 4; ++j) acc[i][j] += a[i] * bb[j];
        }
        __syncthreads();
    }

#pragma unroll
    for (int i = 0; i < 4; ++i) {
        int mg = m0 + ty * 4 + i;
        float sc = (MODE == 2) ? gamma[mg] * rsqrtf(rvar[mg] + BN_EPS) : 1.f;
#pragma unroll
        for (int j = 0; j < 4; ++j)
            Cm[(long)mg * LD + n0 + tx * 4 + j] = acc[i][j] * sc;
    }
}

// ---------------- launch: pure kernel launches, no runtime API calls ----------------
extern "C" void kernel_launch(void* const* d_in, const int* in_sizes, int n_in,
                              void* d_out, int out_size)
{
    const float* x      = (const float*)d_in[0];
    const float* w_qkv  = (const float*)d_in[1];
    const float* w_proj = (const float*)d_in[2];
    const float* gamma  = (const float*)d_in[3];
    const float* beta   = (const float*)d_in[4];
    const float* rmean  = (const float*)d_in[5];
    const float* rvar   = (const float*)d_in[6];
    float* out = (float*)d_out;

    // 1) g_k = Wk @ X   (Wk = w_qkv rows [256,512))
    gemm_big<0, 1, 0><<<dim3(128, 2, BB), 256>>>(w_qkv + CC * CC, x, nullptr,
                                                 nullptr, nullptr, nullptr, nullptr);

    // 2) per-row softmax stats (max, 1/sum) over g_k
    rowstats<<<BB * CC, 256>>>();

    // 3) split-K partials: exp(K-m) @ X^T  -> g_Spp
    gemm_ctx<<<dim3(2, 2, BB * SPLITS), 256>>>(x);

    // 3b) reduce partials -> g_Sp
    reduce_sp<<<512, 256>>>();

    // 4) g_A0 = Wproj @ Wv   (Wv = w_qkv rows [512,768))
    sgemm_small<0><<<dim3(4, 4, 1), 256>>>(w_proj, w_qkv + 2 * CC * CC, nullptr, nullptr);

    // 5) g_U[b] = diag(1/s)-weighted S'^T @ Wq  (Wq = w_qkv rows [0,256))
    sgemm_small<1><<<dim3(4, 4, BB), 256>>>(w_qkv, nullptr, nullptr, nullptr);

    // 6) g_P2[b] = diag(inv) * (A0 @ U[b])
    sgemm_small<2><<<dim3(4, 4, BB), 256>>>(nullptr, nullptr, gamma, rvar);

    // 7) out = relu(P2 @ X + (beta - mean*inv))
    gemm_big<1, 0, 1><<<dim3(128, 2, BB), 256>>>(nullptr, x, out,
                                                 gamma, beta, rmean, rvar);
}

// round 8
// speedup vs baseline: 1.3459x; 1.3459x over previous
#include <cuda_runtime.h>
#include <cuda_bf16.h>
#include <cstdint>

#define BB 8
#define CC 256
#define NNS 16384
#define BN_EPS 1e-5f
#define SPLITS 16

// ---------------- scratch (static device globals; no allocation allowed) ----------------
__device__ __align__(16) float g_k[(size_t)BB * CC * NNS];              // 134 MB: K = Wk @ X
__device__ __align__(16) float g_m[BB * CC];                            // per-row max
__device__ __align__(16) float g_s[BB * CC];                            // per-row 1/sum(exp)
__device__ __align__(16) float g_Spp[(size_t)SPLITS * BB * CC * CC];    // split-K partials
__device__ __align__(16) float g_Sp[BB * CC * CC];                      // S' reduced
__device__ __align__(16) float g_A0[CC * CC];                           // Wproj @ Wv
__device__ __align__(16) float g_U[BB * CC * CC];                       // weighted S'^T @ Wq
__device__ __align__(16) float g_P2[BB * CC * CC];                      // diag(inv) * A0 @ U
__device__ __align__(16) __nv_bfloat16 g_xt_hi[(size_t)BB * NNS * CC];  // X^T hi  [b][n][c]
__device__ __align__(16) __nv_bfloat16 g_xt_lo[(size_t)BB * NNS * CC];  // X^T lo

// ================= helpers (base-sm_103-safe PTX only) =================
__device__ __forceinline__ uint32_t smem_to_u32(const void* p) {
    uint32_t a;
    asm("{ .reg .u64 t; cvta.to.shared.u64 t, %1; cvt.u32.u64 %0, t; }" : "=r"(a) : "l"(p));
    return a;
}
__device__ __forceinline__ void ldsm4(uint32_t* r, uint32_t addr) {
    asm volatile("ldmatrix.sync.aligned.m8n8.x4.shared.b16 {%0,%1,%2,%3}, [%4];"
                 : "=r"(r[0]), "=r"(r[1]), "=r"(r[2]), "=r"(r[3]) : "r"(addr));
}
__device__ __forceinline__ void mma_bf16(float* c, const uint32_t* a, const uint32_t* b) {
    asm volatile("mma.sync.aligned.m16n8k16.row.col.f32.bf16.bf16.f32 "
                 "{%0,%1,%2,%3}, {%4,%5,%6,%7}, {%8,%9}, {%0,%1,%2,%3};"
                 : "+f"(c[0]), "+f"(c[1]), "+f"(c[2]), "+f"(c[3])
                 : "r"(a[0]), "r"(a[1]), "r"(a[2]), "r"(a[3]), "r"(b[0]), "r"(b[1]));
}
__device__ __forceinline__ void cp_async16(uint32_t dst, const void* src) {
    asm volatile("cp.async.cg.shared.global [%0], [%1], 16;" :: "r"(dst), "l"(src));
}
#define CP_COMMIT() asm volatile("cp.async.commit_group;" ::: "memory")
#define CP_WAIT0()  asm volatile("cp.async.wait_group 0;" ::: "memory")

__device__ __forceinline__ uint32_t pack2(float a, float b) {
    union { __nv_bfloat162 v; uint32_t u; } cv;
    cv.v = __floats2bfloat162_rn(a, b);
    return cv.u;
}
__device__ __forceinline__ float hi_of(float a) {
    return __bfloat162float(__float2bfloat16(a));
}

// ---------------- SMEM layout: padded rows of 40 b16 (80 B) -> conflict-free ldmatrix ----------------
#define RSB 80                     // row stride bytes (40 bf16)
#define OFF_AH 0                   // A hi: 128 rows * 80 B = 10240
#define OFF_AL 10240
#define OFF_BH 20480
#define OFF_BL 30720
#define STAGE  40960
#define SMEM_BIG (2 * STAGE)            // 81920
#define SMEM_CTX (2 * STAGE + 512)      // + row-max cache

// ---------------- X transpose + bf16 hi/lo split: x[b][c][n] -> xt[b][n][c] ----------------
__global__ void __launch_bounds__(256)
transpose_split(const float* __restrict__ x)
{
    __shared__ float sm[32][33];
    const int b = blockIdx.z, c0 = blockIdx.y * 32, n0 = blockIdx.x * 32;
    const int tx = threadIdx.x, ty = threadIdx.y;   // 32 x 8
    const float* xs = x + ((size_t)b * CC + c0) * NNS + n0;
#pragma unroll
    for (int i = 0; i < 4; ++i)
        sm[ty + i * 8][tx] = xs[(size_t)(ty + i * 8) * NNS + tx];
    __syncthreads();
    const size_t obase = ((size_t)b * NNS + n0) * CC + c0;
#pragma unroll
    for (int i = 0; i < 4; ++i) {
        int n = ty + i * 8;
        float v = sm[tx][n];
        __nv_bfloat16 h = __float2bfloat16(v);
        g_xt_hi[obase + (size_t)n * CC + tx] = h;
        g_xt_lo[obase + (size_t)n * CC + tx] = __float2bfloat16(v - __bfloat162float(h));
    }
}

// ---------------- big HMMA GEMM: D[b](256x16384) = A(256x256 fp32) @ Xt[b]([n][c] bf16 hi/lo) ----------------
// MODE 0: A = Ap_ (Wk), D -> g_k.   MODE 1: A = g_P2[b], D -> outp with BN bias + ReLU.
template <int MODE>
__global__ void __launch_bounds__(256)
mma_big(const float* __restrict__ Ap_, float* __restrict__ outp,
        const float* __restrict__ gamma, const float* __restrict__ beta,
        const float* __restrict__ rmean, const float* __restrict__ rvar)
{
    extern __shared__ __align__(16) char smem[];
    const int tid = threadIdx.x, lid = tid & 31, wid = tid >> 5;
    const int wm = wid & 1, wn = wid >> 1;
    const int b = blockIdx.z, m0 = blockIdx.y * 128, n0 = blockIdx.x * 128;
    const float* A = ((MODE == 0) ? Ap_ : (g_P2 + (size_t)b * CC * CC)) + (size_t)m0 * CC;
    const __nv_bfloat16* bhg = g_xt_hi + ((size_t)b * NNS + n0) * CC;
    const __nv_bfloat16* blg = g_xt_lo + ((size_t)b * NNS + n0) * CC;
    const uint32_t sb = smem_to_u32(smem);

    float acc[4][4][4];
#pragma unroll
    for (int f = 0; f < 4; ++f)
#pragma unroll
        for (int j = 0; j < 4; ++j)
#pragma unroll
            for (int e = 0; e < 4; ++e) acc[f][j][e] = 0.f;

    auto loadA = [&](int ks, int st) {   // A 128x32 fp32 -> hi/lo bf16 (plain STS)
        char* bp = smem + st * STAGE;
        const float* As = A + ks * 32;
#pragma unroll
        for (int i = 0; i < 4; ++i) {
            int idx = tid + i * 256;             // 0..1023 float4s
            int r = idx >> 3, q = idx & 7;
            float4 v = *reinterpret_cast<const float4*>(As + (size_t)r * CC + q * 4);
            uint32_t h01 = pack2(v.x, v.y), h23 = pack2(v.z, v.w);
            uint32_t l01 = pack2(v.x - hi_of(v.x), v.y - hi_of(v.y));
            uint32_t l23 = pack2(v.z - hi_of(v.z), v.w - hi_of(v.w));
            *reinterpret_cast<uint2*>(bp + OFF_AH + r * RSB + q * 8) = make_uint2(h01, h23);
            *reinterpret_cast<uint2*>(bp + OFF_AL + r * RSB + q * 8) = make_uint2(l01, l23);
        }
    };
    auto loadB = [&](int ks, int st) {   // B 128 n-rows x 32 c, direct bf16 copies via cp.async
        uint32_t dst = sb + st * STAGE;
#pragma unroll
        for (int i = 0; i < 2; ++i) {
            int idx = tid + i * 256;             // 0..511 16B chunks
            int r = idx >> 2, q = idx & 3;
            cp_async16(dst + OFF_BH + r * RSB + q * 16, bhg + (size_t)r * CC + ks * 32 + q * 8);
            cp_async16(dst + OFF_BL + r * RSB + q * 16, blg + (size_t)r * CC + ks * 32 + q * 8);
        }
    };
    auto compute = [&](int st) {
        const uint32_t s0 = sb + st * STAGE;
#pragma unroll
        for (int k16 = 0; k16 < 2; ++k16) {
            const int ko = k16 * 16;
            uint32_t ah[4][4], al[4][4], bhf[2][4], blf[2][4];
            const uint32_t acol = (uint32_t)(ko + ((lid >> 4) << 3)) << 1;
#pragma unroll
            for (int f = 0; f < 4; ++f) {
                uint32_t row = (uint32_t)(wm * 64 + f * 16 + (lid & 15));
                ldsm4(ah[f], s0 + OFF_AH + row * RSB + acol);
                ldsm4(al[f], s0 + OFF_AL + row * RSB + acol);
            }
            const uint32_t bcol = (uint32_t)(ko + (((lid >> 3) & 1) << 3)) << 1;
#pragma unroll
            for (int p = 0; p < 2; ++p) {
                uint32_t nr = (uint32_t)(wn * 32 + p * 16 + (lid & 7) + ((lid >> 4) << 3));
                ldsm4(bhf[p], s0 + OFF_BH + nr * RSB + bcol);
                ldsm4(blf[p], s0 + OFF_BL + nr * RSB + bcol);
            }
#pragma unroll
            for (int f = 0; f < 4; ++f)
#pragma unroll
                for (int j = 0; j < 4; ++j) {
                    const int p = j >> 1, h = j & 1;
                    uint32_t bh2[2] = {bhf[p][h * 2], bhf[p][h * 2 + 1]};
                    uint32_t bl2[2] = {blf[p][h * 2], blf[p][h * 2 + 1]};
                    mma_bf16(acc[f][j], ah[f], bh2);
                    mma_bf16(acc[f][j], ah[f], bl2);
                    mma_bf16(acc[f][j], al[f], bh2);
                }
        }
    };

    loadB(0, 0); CP_COMMIT();
    loadA(0, 0);
    for (int s = 0; s < 8; ++s) {
        CP_WAIT0();
        __syncthreads();
        if (s < 7) { loadB(s + 1, (s + 1) & 1); CP_COMMIT(); loadA(s + 1, (s + 1) & 1); }
        compute(s & 1);
    }

    // epilogue
    float* outb = (MODE == 0 ? g_k : outp) + (size_t)b * CC * NNS;
    const int colb = n0 + wn * 32 + 2 * (lid & 3);
#pragma unroll
    for (int f = 0; f < 4; ++f) {
        const int r0 = m0 + wm * 64 + f * 16 + (lid >> 2);
        float bias0 = 0.f, bias1 = 0.f;
        if (MODE == 1) {
            float i0 = gamma[r0] * rsqrtf(rvar[r0] + BN_EPS);
            float i1 = gamma[r0 + 8] * rsqrtf(rvar[r0 + 8] + BN_EPS);
            bias0 = beta[r0] - rmean[r0] * i0;
            bias1 = beta[r0 + 8] - rmean[r0 + 8] * i1;
        }
#pragma unroll
        for (int j = 0; j < 4; ++j) {
            const int cc0 = colb + j * 8;
            float2 v0 = make_float2(acc[f][j][0], acc[f][j][1]);
            float2 v1 = make_float2(acc[f][j][2], acc[f][j][3]);
            if (MODE == 1) {
                v0.x = fmaxf(v0.x + bias0, 0.f); v0.y = fmaxf(v0.y + bias0, 0.f);
                v1.x = fmaxf(v1.x + bias1, 0.f); v1.y = fmaxf(v1.y + bias1, 0.f);
            }
            *reinterpret_cast<float2*>(outb + (size_t)r0 * NNS + cc0)       = v0;
            *reinterpret_cast<float2*>(outb + (size_t)(r0 + 8) * NNS + cc0) = v1;
        }
    }
}

// ---------------- ctx HMMA GEMM: S'_partial[split][b](128x128 tile) = exp(K-m) @ X^T over 1024 n ----------------
__global__ void __launch_bounds__(256)
mma_ctx(const float* __restrict__ x)
{
    extern __shared__ __align__(16) char smem[];
    float* ms = reinterpret_cast<float*>(smem + 2 * STAGE);
    const int tid = threadIdx.x, lid = tid & 31, wid = tid >> 5;
    const int wm = wid & 1, wn = wid >> 1;
    const int o0 = (blockIdx.x >> 1) * 128, c0 = (blockIdx.x & 1) * 128;
    const int split = blockIdx.y, b = blockIdx.z;
    const uint32_t sb = smem_to_u32(smem);

    if (tid < 128) ms[tid] = g_m[b * CC + o0 + tid];
    __syncthreads();

    const float* kbase = g_k + ((size_t)b * CC + o0) * NNS + (size_t)split * 1024;
    const float* xbase = x + ((size_t)b * CC + c0) * NNS + (size_t)split * 1024;

    float acc[4][4][4];
#pragma unroll
    for (int f = 0; f < 4; ++f)
#pragma unroll
        for (int j = 0; j < 4; ++j)
#pragma unroll
            for (int e = 0; e < 4; ++e) acc[f][j][e] = 0.f;

    auto loadTiles = [&](int s, int st) {
        char* bp = smem + st * STAGE;
        const int nb = s * 32;
#pragma unroll
        for (int i = 0; i < 4; ++i) {
            int idx = tid + i * 256;             // 0..1023 float4s
            int r = idx >> 3, q = idx & 7;
            float4 v = *reinterpret_cast<const float4*>(kbase + (size_t)r * NNS + nb + q * 4);
            float4 u = *reinterpret_cast<const float4*>(xbase + (size_t)r * NNS + nb + q * 4);
            float mr = ms[r];
            float ex = __expf(v.x - mr), ey = __expf(v.y - mr);
            float ez = __expf(v.z - mr), ew = __expf(v.w - mr);
            *reinterpret_cast<uint2*>(bp + OFF_AH + r * RSB + q * 8) =
                make_uint2(pack2(ex, ey), pack2(ez, ew));
            *reinterpret_cast<uint2*>(bp + OFF_AL + r * RSB + q * 8) =
                make_uint2(pack2(ex - hi_of(ex), ey - hi_of(ey)),
                           pack2(ez - hi_of(ez), ew - hi_of(ew)));
            *reinterpret_cast<uint2*>(bp + OFF_BH + r * RSB + q * 8) =
                make_uint2(pack2(u.x, u.y), pack2(u.z, u.w));
            *reinterpret_cast<uint2*>(bp + OFF_BL + r * RSB + q * 8) =
                make_uint2(pack2(u.x - hi_of(u.x), u.y - hi_of(u.y)),
                           pack2(u.z - hi_of(u.z), u.w - hi_of(u.w)));
        }
    };
    auto compute = [&](int st) {
        const uint32_t s0 = sb + st * STAGE;
#pragma unroll
        for (int k16 = 0; k16 < 2; ++k16) {
            const int ko = k16 * 16;
            uint32_t ah[4][4], al[4][4], bhf[2][4], blf[2][4];
            const uint32_t acol = (uint32_t)(ko + ((lid >> 4) << 3)) << 1;
#pragma unroll
            for (int f = 0; f < 4; ++f) {
                uint32_t row = (uint32_t)(wm * 64 + f * 16 + (lid & 15));
                ldsm4(ah[f], s0 + OFF_AH + row * RSB + acol);
                ldsm4(al[f], s0 + OFF_AL + row * RSB + acol);
            }
            const uint32_t bcol = (uint32_t)(ko + (((lid >> 3) & 1) << 3)) << 1;
#pragma unroll
            for (int p = 0; p < 2; ++p) {
                uint32_t nr = (uint32_t)(wn * 32 + p * 16 + (lid & 7) + ((lid >> 4) << 3));
                ldsm4(bhf[p], s0 + OFF_BH + nr * RSB + bcol);
                ldsm4(blf[p], s0 + OFF_BL + nr * RSB + bcol);
            }
#pragma unroll
            for (int f = 0; f < 4; ++f)
#pragma unroll
                for (int j = 0; j < 4; ++j) {
                    const int p = j >> 1, h = j & 1;
                    uint32_t bh2[2] = {bhf[p][h * 2], bhf[p][h * 2 + 1]};
                    uint32_t bl2[2] = {blf[p][h * 2], blf[p][h * 2 + 1]};
                    mma_bf16(acc[f][j], ah[f], bh2);
                    mma_bf16(acc[f][j], ah[f], bl2);
                    mma_bf16(acc[f][j], al[f], bh2);
                }
        }
    };

    loadTiles(0, 0);
    for (int s = 0; s < 32; ++s) {
        __syncthreads();
        if (s < 31) loadTiles(s + 1, (s + 1) & 1);
        compute(s & 1);
    }

    float* dstb = g_Spp + ((size_t)split * BB + b) * CC * CC;
    const int colb = c0 + wn * 32 + 2 * (lid & 3);
#pragma unroll
    for (int f = 0; f < 4; ++f) {
        const int r0 = o0 + wm * 64 + f * 16 + (lid >> 2);
#pragma unroll
        for (int j = 0; j < 4; ++j) {
            const int cc0 = colb + j * 8;
            *reinterpret_cast<float2*>(dstb + (size_t)r0 * CC + cc0) =
                make_float2(acc[f][j][0], acc[f][j][1]);
            *reinterpret_cast<float2*>(dstb + (size_t)(r0 + 8) * CC + cc0) =
                make_float2(acc[f][j][2], acc[f][j][3]);
        }
    }
}

// ---------------- per-row max + 1/sum(exp) over N=16384 ----------------
__global__ void __launch_bounds__(256)
rowstats()
{
    const long row = blockIdx.x;
    const float4* kr = reinterpret_cast<const float4*>(g_k) + row * (NNS / 4);
    const int t = threadIdx.x;

    float4 v[16];
    float mx = -3.402823466e38f;
#pragma unroll
    for (int i = 0; i < 16; ++i) {
        v[i] = kr[t + (i << 8)];
        mx = fmaxf(mx, fmaxf(fmaxf(v[i].x, v[i].y), fmaxf(v[i].z, v[i].w)));
    }
    __shared__ float red[8];
    __shared__ float bmax;
#pragma unroll
    for (int o = 16; o; o >>= 1) mx = fmaxf(mx, __shfl_xor_sync(0xffffffffu, mx, o));
    if ((t & 31) == 0) red[t >> 5] = mx;
    __syncthreads();
    if (t < 32) {
        float x2 = (t < 8) ? red[t] : -3.402823466e38f;
#pragma unroll
        for (int o = 4; o; o >>= 1) x2 = fmaxf(x2, __shfl_xor_sync(0xffffffffu, x2, o));
        if (t == 0) bmax = x2;
    }
    __syncthreads();
    const float m = bmax;

    float s = 0.f;
#pragma unroll
    for (int i = 0; i < 16; ++i)
        s += __expf(v[i].x - m) + __expf(v[i].y - m) + __expf(v[i].z - m) + __expf(v[i].w - m);
#pragma unroll
    for (int o = 16; o; o >>= 1) s += __shfl_xor_sync(0xffffffffu, s, o);
    if ((t & 31) == 0) red[t >> 5] = s;
    __syncthreads();
    if (t < 32) {
        float x2 = (t < 8) ? red[t] : 0.f;
#pragma unroll
        for (int o = 4; o; o >>= 1) x2 += __shfl_xor_sync(0xffffffffu, x2, o);
        if (t == 0) { g_m[row] = m; g_s[row] = 1.0f / x2; }
    }
}

// ---------------- reduce the 16 split partials into g_Sp ----------------
__global__ void __launch_bounds__(256)
reduce_sp()
{
    const int idx = blockIdx.x * 256 + threadIdx.x;
    const float4* src = reinterpret_cast<const float4*>(g_Spp);
    float4 a = make_float4(0.f, 0.f, 0.f, 0.f);
#pragma unroll
    for (int s = 0; s < SPLITS; ++s) {
        float4 v = src[(long)s * (BB * CC * CC / 4) + idx];
        a.x += v.x; a.y += v.y; a.z += v.z; a.w += v.w;
    }
    reinterpret_cast<float4*>(g_Sp)[idx] = a;
}

// ---------------- small 256^3 GEMMs (fp32) ----------------
template <int MODE>
__global__ void __launch_bounds__(256)
sgemm_small(const float* __restrict__ in0, const float* __restrict__ in1,
            const float* __restrict__ gamma, const float* __restrict__ rvar)
{
    const int LD = CC;
    const int b = blockIdx.z;
    const float* A = (MODE == 0) ? in0 : (MODE == 1) ? (g_Sp + (long)b * CC * CC) : g_A0;
    const float* Bm = (MODE == 0) ? in1 : (MODE == 1) ? in0 : (g_U + (long)b * CC * CC);
    float* Cm = (MODE == 0) ? g_A0 : (MODE == 1) ? (g_U + (long)b * CC * CC)
                                                  : (g_P2 + (long)b * CC * CC);
    const float* ks = (MODE == 1) ? (g_s + (long)b * CC) : nullptr;
    const int m0 = blockIdx.y * 64, n0 = blockIdx.x * 64;

    __shared__ float As[16][65];
    __shared__ float Bs[16][65];

    const int tid = threadIdx.x;
    const int tx = tid & 15, ty = tid >> 4;
    float acc[4][4] = {};

    for (int k0 = 0; k0 < CC; k0 += 16) {
#pragma unroll
        for (int p = 0; p < 4; ++p) {
            int idx = tid + p * 256;
            if (MODE == 1) {
                int kk = idx >> 6, mm = idx & 63;
                As[kk][mm] = A[(long)(k0 + kk) * LD + m0 + mm] * ks[k0 + kk];
            } else {
                int mm = idx >> 4, kk = idx & 15;
                As[kk][mm] = A[(long)(m0 + mm) * LD + k0 + kk];
            }
            int kk2 = idx >> 6, nn2 = idx & 63;
            Bs[kk2][nn2] = Bm[(long)(k0 + kk2) * LD + n0 + nn2];
        }
        __syncthreads();
#pragma unroll
        for (int kk = 0; kk < 16; ++kk) {
            float a[4], bb[4];
#pragma unroll
            for (int i = 0; i < 4; ++i) { a[i] = As[kk][ty * 4 + i]; bb[i] = Bs[kk][tx * 4 + i]; }
#pragma unroll
            for (int i = 0; i < 4; ++i)
#pragma unroll
                for (int j = 0; j < 4; ++j) acc[i][j] += a[i] * bb[j];
        }
        __syncthreads();
    }

#pragma unroll
    for (int i = 0; i < 4; ++i) {
        int mg = m0 + ty * 4 + i;
        float sc = (MODE == 2) ? gamma[mg] * rsqrtf(rvar[mg] + BN_EPS) : 1.f;
#pragma unroll
        for (int j = 0; j < 4; ++j)
            Cm[(long)mg * LD + n0 + tx * 4 + j] = acc[i][j] * sc;
    }
}

// ---------------- launch ----------------
extern "C" void kernel_launch(void* const* d_in, const int* in_sizes, int n_in,
                              void* d_out, int out_size)
{
    const float* x      = (const float*)d_in[0];
    const float* w_qkv  = (const float*)d_in[1];
    const float* w_proj = (const float*)d_in[2];
    const float* gamma  = (const float*)d_in[3];
    const float* beta   = (const float*)d_in[4];
    const float* rmean  = (const float*)d_in[5];
    const float* rvar   = (const float*)d_in[6];
    float* out = (float*)d_out;

    cudaFuncSetAttribute((const void*)mma_big<0>, cudaFuncAttributeMaxDynamicSharedMemorySize, SMEM_BIG);
    cudaFuncSetAttribute((const void*)mma_big<1>, cudaFuncAttributeMaxDynamicSharedMemorySize, SMEM_BIG);
    cudaFuncSetAttribute((const void*)mma_ctx,    cudaFuncAttributeMaxDynamicSharedMemorySize, SMEM_CTX);

    // 0) Xt hi/lo = transpose + bf16-split of X
    transpose_split<<<dim3(NNS / 32, CC / 32, BB), dim3(32, 8)>>>(x);

    // 1) g_k = Wk @ X   (Wk = w_qkv rows [256,512))
    mma_big<0><<<dim3(NNS / 128, 2, BB), 256, SMEM_BIG>>>(w_qkv + CC * CC, nullptr,
                                                          nullptr, nullptr, nullptr, nullptr);

    // 2) per-row softmax stats
    rowstats<<<BB * CC, 256>>>();

    // 3) split-K partials: exp(K-m) @ X^T -> g_Spp
    mma_ctx<<<dim3(4, SPLITS, BB), 256, SMEM_CTX>>>(x);

    // 3b) reduce partials -> g_Sp
    reduce_sp<<<512, 256>>>();

    // 4) g_A0 = Wproj @ Wv
    sgemm_small<0><<<dim3(4, 4, 1), 256>>>(w_proj, w_qkv + 2 * CC * CC, nullptr, nullptr);

    // 5) g_U[b] = diag(1/s)-weighted S'^T @ Wq
    sgemm_small<1><<<dim3(4, 4, BB), 256>>>(w_qkv, nullptr, nullptr, nullptr);

    // 6) g_P2[b] = diag(inv) * (A0 @ U[b])
    sgemm_small<2><<<dim3(4, 4, BB), 256>>>(nullptr, nullptr, gamma, rvar);

    // 7) out = relu(P2 @ X + (beta - mean*inv))
    mma_big<1><<<dim3(NNS / 128, 2, BB), 256, SMEM_BIG>>>(nullptr, out,
                                                          gamma, beta, rmean, rvar);
}

// round 11
// speedup vs baseline: 1.9494x; 1.4484x over previous
#include <cuda_runtime.h>
#include <cuda_bf16.h>
#include <cstdint>

#define BB 8
#define CC 256
#define NNS 16384
#define BN_EPS 1e-5f
#define SPLITS 16

// ---------------- scratch (static device globals; no allocation allowed) ----------------
__device__ __align__(16) float g_k[(size_t)BB * CC * NNS];              // fp32 K = Wk @ X
__device__ __align__(16) float g_m[BB * CC];                            // per-row max
__device__ __align__(16) float g_s[BB * CC];                            // per-row 1/sum(exp)
__device__ __align__(16) float g_Spp[(size_t)SPLITS * BB * CC * CC];    // split-K partials
__device__ __align__(16) float g_Sp[BB * CC * CC];                      // S' reduced
__device__ __align__(16) float g_A0[CC * CC];                           // Wproj @ Wv
__device__ __align__(16) float g_U[BB * CC * CC];                       // weighted S'^T @ Wq
__device__ __align__(16) float g_P2[BB * CC * CC];                      // diag(inv) * A0 @ U (fp32, as in R8)
__device__ __align__(16) __nv_bfloat16 g_xt_h[(size_t)BB * NNS * CC];   // X^T hi [b][n][c]
__device__ __align__(16) __nv_bfloat16 g_xt_l[(size_t)BB * NNS * CC];   // X^T lo
__device__ __align__(16) __nv_bfloat16 g_xn_h[(size_t)BB * CC * NNS];   // X   hi [b][c][n]
__device__ __align__(16) __nv_bfloat16 g_xn_l[(size_t)BB * CC * NNS];   // X   lo
__device__ __align__(16) __nv_bfloat16 g_e_h[(size_t)BB * CC * NNS];    // exp(K-m) hi [b][o][n]
__device__ __align__(16) __nv_bfloat16 g_e_l[(size_t)BB * CC * NNS];    // exp(K-m) lo

// ================= helpers (base-sm_103-safe PTX only) =================
__device__ __forceinline__ uint32_t smem_to_u32(const void* p) {
    uint32_t a;
    asm("{ .reg .u64 t; cvta.to.shared.u64 t, %1; cvt.u32.u64 %0, t; }" : "=r"(a) : "l"(p));
    return a;
}
__device__ __forceinline__ void ldsm4(uint32_t* r, uint32_t addr) {
    asm volatile("ldmatrix.sync.aligned.m8n8.x4.shared.b16 {%0,%1,%2,%3}, [%4];"
                 : "=r"(r[0]), "=r"(r[1]), "=r"(r[2]), "=r"(r[3]) : "r"(addr));
}
__device__ __forceinline__ void mma_bf16(float* c, const uint32_t* a, const uint32_t* b) {
    asm volatile("mma.sync.aligned.m16n8k16.row.col.f32.bf16.bf16.f32 "
                 "{%0,%1,%2,%3}, {%4,%5,%6,%7}, {%8,%9}, {%0,%1,%2,%3};"
                 : "+f"(c[0]), "+f"(c[1]), "+f"(c[2]), "+f"(c[3])
                 : "r"(a[0]), "r"(a[1]), "r"(a[2]), "r"(a[3]), "r"(b[0]), "r"(b[1]));
}
__device__ __forceinline__ void cp_async16(uint32_t dst, const void* src) {
    asm volatile("cp.async.cg.shared.global [%0], [%1], 16;" :: "r"(dst), "l"(src));
}
#define CP_COMMIT() asm volatile("cp.async.commit_group;" ::: "memory")
#define CP_WAIT0()  asm volatile("cp.async.wait_group 0;" ::: "memory")

__device__ __forceinline__ uint32_t pack2(float a, float b) {
    union { __nv_bfloat162 v; uint32_t u; } cv;
    cv.v = __floats2bfloat162_rn(a, b);
    return cv.u;
}
__device__ __forceinline__ float hi_of(float a) {
    return __bfloat162float(__float2bfloat16(a));
}

// ---------------- SMEM layout: padded rows of 40 b16 (80 B) -> conflict-free ldmatrix ----------------
#define RSB 80
#define OFF_AH 0
#define OFF_AL 10240
#define OFF_BH 20480
#define OFF_BL 30720
#define STAGE  40960
#define SMEM_MMA (2 * STAGE)            // 81920, double buffered

// ---------------- X transpose + bf16 hi/lo split (both layouts) ----------------
__global__ void __launch_bounds__(256)
transpose_split(const float* __restrict__ x)
{
    __shared__ float sm[32][33];
    const int b = blockIdx.z, c0 = blockIdx.y * 32, n0 = blockIdx.x * 32;
    const int tx = threadIdx.x, ty = threadIdx.y;   // 32 x 8
    const float* xs = x + ((size_t)b * CC + c0) * NNS + n0;
    float v[4];
#pragma unroll
    for (int i = 0; i < 4; ++i) {
        v[i] = xs[(size_t)(ty + i * 8) * NNS + tx];
        sm[ty + i * 8][tx] = v[i];
    }
    // straight layout [c][n] bf16 hi/lo (for ctx B operand)
    const size_t nbase = ((size_t)b * CC + c0) * NNS + n0;
#pragma unroll
    for (int i = 0; i < 4; ++i) {
        int c = ty + i * 8;
        __nv_bfloat16 h = __float2bfloat16(v[i]);
        g_xn_h[nbase + (size_t)c * NNS + tx] = h;
        g_xn_l[nbase + (size_t)c * NNS + tx] = __float2bfloat16(v[i] - __bfloat162float(h));
    }
    __syncthreads();
    // transposed layout [n][c] bf16 hi/lo (for big GEMM B operand)
    const size_t obase = ((size_t)b * NNS + n0) * CC + c0;
#pragma unroll
    for (int i = 0; i < 4; ++i) {
        int n = ty + i * 8;
        float f = sm[tx][n];
        __nv_bfloat16 h = __float2bfloat16(f);
        g_xt_h[obase + (size_t)n * CC + tx] = h;
        g_xt_l[obase + (size_t)n * CC + tx] = __float2bfloat16(f - __bfloat162float(h));
    }
}

// ---------------- big HMMA GEMM (R8 VERBATIM): D[b] = A(fp32, split in-loop) @ Xt[b] ----------------
// MODE 0: A = Ap_ (Wk), D -> g_k.   MODE 1: A = g_P2[b], D -> outp with BN bias + ReLU.
template <int MODE>
__global__ void __launch_bounds__(256)
mma_big(const float* __restrict__ Ap_, float* __restrict__ outp,
        const float* __restrict__ gamma, const float* __restrict__ beta,
        const float* __restrict__ rmean, const float* __restrict__ rvar)
{
    extern __shared__ __align__(16) char smem[];
    const int tid = threadIdx.x, lid = tid & 31, wid = tid >> 5;
    const int wm = wid & 1, wn = wid >> 1;
    const int b = blockIdx.z, m0 = blockIdx.y * 128, n0 = blockIdx.x * 128;
    const float* A = ((MODE == 0) ? Ap_ : (g_P2 + (size_t)b * CC * CC)) + (size_t)m0 * CC;
    const __nv_bfloat16* bhg = g_xt_h + ((size_t)b * NNS + n0) * CC;
    const __nv_bfloat16* blg = g_xt_l + ((size_t)b * NNS + n0) * CC;
    const uint32_t sb = smem_to_u32(smem);

    float acc[4][4][4];
#pragma unroll
    for (int f = 0; f < 4; ++f)
#pragma unroll
        for (int j = 0; j < 4; ++j)
#pragma unroll
            for (int e = 0; e < 4; ++e) acc[f][j][e] = 0.f;

    auto loadA = [&](int ks, int st) {   // A 128x32 fp32 -> hi/lo bf16 (plain STS)
        char* bp = smem + st * STAGE;
        const float* As = A + ks * 32;
#pragma unroll
        for (int i = 0; i < 4; ++i) {
            int idx = tid + i * 256;             // 0..1023 float4s
            int r = idx >> 3, q = idx & 7;
            float4 v = *reinterpret_cast<const float4*>(As + (size_t)r * CC + q * 4);
            uint32_t h01 = pack2(v.x, v.y), h23 = pack2(v.z, v.w);
            uint32_t l01 = pack2(v.x - hi_of(v.x), v.y - hi_of(v.y));
            uint32_t l23 = pack2(v.z - hi_of(v.z), v.w - hi_of(v.w));
            *reinterpret_cast<uint2*>(bp + OFF_AH + r * RSB + q * 8) = make_uint2(h01, h23);
            *reinterpret_cast<uint2*>(bp + OFF_AL + r * RSB + q * 8) = make_uint2(l01, l23);
        }
    };
    auto loadB = [&](int ks, int st) {   // B 128 n-rows x 32 c, direct bf16 copies via cp.async
        uint32_t dst = sb + st * STAGE;
#pragma unroll
        for (int i = 0; i < 2; ++i) {
            int idx = tid + i * 256;             // 0..511 16B chunks
            int r = idx >> 2, q = idx & 3;
            cp_async16(dst + OFF_BH + r * RSB + q * 16, bhg + (size_t)r * CC + ks * 32 + q * 8);
            cp_async16(dst + OFF_BL + r * RSB + q * 16, blg + (size_t)r * CC + ks * 32 + q * 8);
        }
    };
    auto compute = [&](int st) {
        const uint32_t s0 = sb + st * STAGE;
#pragma unroll
        for (int k16 = 0; k16 < 2; ++k16) {
            const int ko = k16 * 16;
            uint32_t ah[4][4], al[4][4], bhf[2][4], blf[2][4];
            const uint32_t acol = (uint32_t)(ko + ((lid >> 4) << 3)) << 1;
#pragma unroll
            for (int f = 0; f < 4; ++f) {
                uint32_t row = (uint32_t)(wm * 64 + f * 16 + (lid & 15));
                ldsm4(ah[f], s0 + OFF_AH + row * RSB + acol);
                ldsm4(al[f], s0 + OFF_AL + row * RSB + acol);
            }
            const uint32_t bcol = (uint32_t)(ko + (((lid >> 3) & 1) << 3)) << 1;
#pragma unroll
            for (int p = 0; p < 2; ++p) {
                uint32_t nr = (uint32_t)(wn * 32 + p * 16 + (lid & 7) + ((lid >> 4) << 3));
                ldsm4(bhf[p], s0 + OFF_BH + nr * RSB + bcol);
                ldsm4(blf[p], s0 + OFF_BL + nr * RSB + bcol);
            }
#pragma unroll
            for (int f = 0; f < 4; ++f)
#pragma unroll
                for (int j = 0; j < 4; ++j) {
                    const int p = j >> 1, h = j & 1;
                    uint32_t bh2[2] = {bhf[p][h * 2], bhf[p][h * 2 + 1]};
                    uint32_t bl2[2] = {blf[p][h * 2], blf[p][h * 2 + 1]};
                    mma_bf16(acc[f][j], ah[f], bh2);
                    mma_bf16(acc[f][j], ah[f], bl2);
                    mma_bf16(acc[f][j], al[f], bh2);
                }
        }
    };

    loadB(0, 0); CP_COMMIT();
    loadA(0, 0);
    for (int s = 0; s < 8; ++s) {
        CP_WAIT0();
        __syncthreads();
        if (s < 7) { loadB(s + 1, (s + 1) & 1); CP_COMMIT(); loadA(s + 1, (s + 1) & 1); }
        compute(s & 1);
    }

    // epilogue (R8 verbatim)
    float* outb = (MODE == 0 ? g_k : outp) + (size_t)b * CC * NNS;
    const int colb = n0 + wn * 32 + 2 * (lid & 3);
#pragma unroll
    for (int f = 0; f < 4; ++f) {
        const int r0 = m0 + wm * 64 + f * 16 + (lid >> 2);
        float bias0 = 0.f, bias1 = 0.f;
        if (MODE == 1) {
            float i0 = gamma[r0] * rsqrtf(rvar[r0] + BN_EPS);
            float i1 = gamma[r0 + 8] * rsqrtf(rvar[r0 + 8] + BN_EPS);
            bias0 = beta[r0] - rmean[r0] * i0;
            bias1 = beta[r0 + 8] - rmean[r0 + 8] * i1;
        }
#pragma unroll
        for (int j = 0; j < 4; ++j) {
            const int cc0 = colb + j * 8;
            float2 v0 = make_float2(acc[f][j][0], acc[f][j][1]);
            float2 v1 = make_float2(acc[f][j][2], acc[f][j][3]);
            if (MODE == 1) {
                v0.x = fmaxf(v0.x + bias0, 0.f); v0.y = fmaxf(v0.y + bias0, 0.f);
                v1.x = fmaxf(v1.x + bias1, 0.f); v1.y = fmaxf(v1.y + bias1, 0.f);
            }
            *reinterpret_cast<float2*>(outb + (size_t)r0 * NNS + cc0)       = v0;
            *reinterpret_cast<float2*>(outb + (size_t)(r0 + 8) * NNS + cc0) = v1;
        }
    }
}

// ---------------- ctx HMMA GEMM: S'_partial = E(precomputed hi/lo) @ Xn(hi/lo)^T over 1024 n ----------------
__global__ void __launch_bounds__(256)
mma_ctx()
{
    extern __shared__ __align__(16) char smem[];
    const int tid = threadIdx.x, lid = tid & 31, wid = tid >> 5;
    const int wm = wid & 1, wn = wid >> 1;
    const int o0 = (blockIdx.x >> 1) * 128, c0 = (blockIdx.x & 1) * 128;
    const int split = blockIdx.y, b = blockIdx.z;
    const uint32_t sb = smem_to_u32(smem);

    const size_t ko0 = (size_t)split * 1024;
    const __nv_bfloat16* ehg = g_e_h + ((size_t)b * CC + o0) * NNS + ko0;
    const __nv_bfloat16* elg = g_e_l + ((size_t)b * CC + o0) * NNS + ko0;
    const __nv_bfloat16* xhg = g_xn_h + ((size_t)b * CC + c0) * NNS + ko0;
    const __nv_bfloat16* xlg = g_xn_l + ((size_t)b * CC + c0) * NNS + ko0;

    float acc[4][4][4];
#pragma unroll
    for (int f = 0; f < 4; ++f)
#pragma unroll
        for (int j = 0; j < 4; ++j)
#pragma unroll
            for (int e = 0; e < 4; ++e) acc[f][j][e] = 0.f;

    auto loadT = [&](int ks, int st) {   // all four streams, pure cp.async (clone of proven loadB)
        uint32_t dst = sb + st * STAGE;
#pragma unroll
        for (int i = 0; i < 2; ++i) {
            int idx = tid + i * 256;             // 0..511 16B chunks
            int r = idx >> 2, q = idx & 3;
            size_t so = (size_t)r * NNS + (size_t)ks * 32 + q * 8;
            cp_async16(dst + OFF_AH + r * RSB + q * 16, ehg + so);
            cp_async16(dst + OFF_AL + r * RSB + q * 16, elg + so);
            cp_async16(dst + OFF_BH + r * RSB + q * 16, xhg + so);
            cp_async16(dst + OFF_BL + r * RSB + q * 16, xlg + so);
        }
    };
    auto compute = [&](int st) {
        const uint32_t s0 = sb + st * STAGE;
#pragma unroll
        for (int k16 = 0; k16 < 2; ++k16) {
            const int ko = k16 * 16;
            uint32_t ah[4][4], al[4][4], bhf[2][4], blf[2][4];
            const uint32_t acol = (uint32_t)(ko + ((lid >> 4) << 3)) << 1;
#pragma unroll
            for (int f = 0; f < 4; ++f) {
                uint32_t row = (uint32_t)(wm * 64 + f * 16 + (lid & 15));
                ldsm4(ah[f], s0 + OFF_AH + row * RSB + acol);
                ldsm4(al[f], s0 + OFF_AL + row * RSB + acol);
            }
            const uint32_t bcol = (uint32_t)(ko + (((lid >> 3) & 1) << 3)) << 1;
#pragma unroll
            for (int p = 0; p < 2; ++p) {
                uint32_t nr = (uint32_t)(wn * 32 + p * 16 + (lid & 7) + ((lid >> 4) << 3));
                ldsm4(bhf[p], s0 + OFF_BH + nr * RSB + bcol);
                ldsm4(blf[p], s0 + OFF_BL + nr * RSB + bcol);
            }
#pragma unroll
            for (int f = 0; f < 4; ++f)
#pragma unroll
                for (int j = 0; j < 4; ++j) {
                    const int p = j >> 1, h = j & 1;
                    uint32_t bh2[2] = {bhf[p][h * 2], bhf[p][h * 2 + 1]};
                    uint32_t bl2[2] = {blf[p][h * 2], blf[p][h * 2 + 1]};
                    mma_bf16(acc[f][j], ah[f], bh2);
                    mma_bf16(acc[f][j], ah[f], bl2);
                    mma_bf16(acc[f][j], al[f], bh2);
                }
        }
    };

    loadT(0, 0); CP_COMMIT();
    for (int s = 0; s < 32; ++s) {
        CP_WAIT0();
        __syncthreads();
        if (s < 31) { loadT(s + 1, (s + 1) & 1); CP_COMMIT(); }
        compute(s & 1);
    }

    // epilogue (R8 verbatim)
    float* dstb = g_Spp + ((size_t)split * BB + b) * CC * CC;
    const int colb = c0 + wn * 32 + 2 * (lid & 3);
#pragma unroll
    for (int f = 0; f < 4; ++f) {
        const int r0 = o0 + wm * 64 + f * 16 + (lid >> 2);
#pragma unroll
        for (int j = 0; j < 4; ++j) {
            const int cc0 = colb + j * 8;
            *reinterpret_cast<float2*>(dstb + (size_t)r0 * CC + cc0) =
                make_float2(acc[f][j][0], acc[f][j][1]);
            *reinterpret_cast<float2*>(dstb + (size_t)(r0 + 8) * CC + cc0) =
                make_float2(acc[f][j][2], acc[f][j][3]);
        }
    }
}

// ---------------- per-row max + 1/sum(exp) + E=exp(K-m) bf16 hi/lo writeback ----------------
__global__ void __launch_bounds__(256)
rowstats_econv()
{
    const size_t row = blockIdx.x;  // 0..2047 == b*256 + o
    const float4* kr = reinterpret_cast<const float4*>(g_k) + row * (NNS / 4);
    const int t = threadIdx.x;

    float4 v[16];
    float mx = -3.402823466e38f;
#pragma unroll
    for (int i = 0; i < 16; ++i) {
        v[i] = kr[t + (i << 8)];
        mx = fmaxf(mx, fmaxf(fmaxf(v[i].x, v[i].y), fmaxf(v[i].z, v[i].w)));
    }
    __shared__ float red[8];
    __shared__ float bmax;
#pragma unroll
    for (int o = 16; o; o >>= 1) mx = fmaxf(mx, __shfl_xor_sync(0xffffffffu, mx, o));
    if ((t & 31) == 0) red[t >> 5] = mx;
    __syncthreads();
    if (t < 32) {
        float x2 = (t < 8) ? red[t] : -3.402823466e38f;
#pragma unroll
        for (int o = 4; o; o >>= 1) x2 = fmaxf(x2, __shfl_xor_sync(0xffffffffu, x2, o));
        if (t == 0) bmax = x2;
    }
    __syncthreads();
    const float m = bmax;

    uint2* eh = reinterpret_cast<uint2*>(g_e_h + row * NNS);
    uint2* el = reinterpret_cast<uint2*>(g_e_l + row * NNS);
    float s = 0.f;
#pragma unroll
    for (int i = 0; i < 16; ++i) {
        float ex = __expf(v[i].x - m), ey = __expf(v[i].y - m);
        float ez = __expf(v[i].z - m), ew = __expf(v[i].w - m);
        s += ex + ey + ez + ew;
        const int q = t + (i << 8);                 // float4 index within row
        eh[q] = make_uint2(pack2(ex, ey), pack2(ez, ew));
        el[q] = make_uint2(pack2(ex - hi_of(ex), ey - hi_of(ey)),
                           pack2(ez - hi_of(ez), ew - hi_of(ew)));
    }
#pragma unroll
    for (int o = 16; o; o >>= 1) s += __shfl_xor_sync(0xffffffffu, s, o);
    if ((t & 31) == 0) red[t >> 5] = s;
    __syncthreads();
    if (t < 32) {
        float x2 = (t < 8) ? red[t] : 0.f;
#pragma unroll
        for (int o = 4; o; o >>= 1) x2 += __shfl_xor_sync(0xffffffffu, x2, o);
        if (t == 0) { g_m[row] = m; g_s[row] = 1.0f / x2; }
    }
}

// ---------------- reduce the 16 split partials into g_Sp ----------------
__global__ void __launch_bounds__(256)
reduce_sp()
{
    const int idx = blockIdx.x * 256 + threadIdx.x;
    const float4* src = reinterpret_cast<const float4*>(g_Spp);
    float4 a = make_float4(0.f, 0.f, 0.f, 0.f);
#pragma unroll
    for (int s = 0; s < SPLITS; ++s) {
        float4 v = src[(long)s * (BB * CC * CC / 4) + idx];
        a.x += v.x; a.y += v.y; a.z += v.z; a.w += v.w;
    }
    reinterpret_cast<float4*>(g_Sp)[idx] = a;
}

// ---------------- small 256^3 GEMMs (R8 VERBATIM, fp32 P2 output) ----------------
template <int MODE>
__global__ void __launch_bounds__(256)
sgemm_small(const float* __restrict__ in0, const float* __restrict__ in1,
            const float* __restrict__ gamma, const float* __restrict__ rvar)
{
    const int LD = CC;
    const int b = blockIdx.z;
    const float* A = (MODE == 0) ? in0 : (MODE == 1) ? (g_Sp + (long)b * CC * CC) : g_A0;
    const float* Bm = (MODE == 0) ? in1 : (MODE == 1) ? in0 : (g_U + (long)b * CC * CC);
    float* Cm = (MODE == 0) ? g_A0 : (MODE == 1) ? (g_U + (long)b * CC * CC)
                                                  : (g_P2 + (long)b * CC * CC);
    const float* ks = (MODE == 1) ? (g_s + (long)b * CC) : nullptr;
    const int m0 = blockIdx.y * 64, n0 = blockIdx.x * 64;

    __shared__ float As[16][65];
    __shared__ float Bs[16][65];

    const int tid = threadIdx.x;
    const int tx = tid & 15, ty = tid >> 4;
    float acc[4][4] = {};

    for (int k0 = 0; k0 < CC; k0 += 16) {
#pragma unroll
        for (int p = 0; p < 4; ++p) {
            int idx = tid + p * 256;
            if (MODE == 1) {
                int kk = idx >> 6, mm = idx & 63;
                As[kk][mm] = A[(long)(k0 + kk) * LD + m0 + mm] * ks[k0 + kk];
            } else {
                int mm = idx >> 4, kk = idx & 15;
                As[kk][mm] = A[(long)(m0 + mm) * LD + k0 + kk];
            }
            int kk2 = idx >> 6, nn2 = idx & 63;
            Bs[kk2][nn2] = Bm[(long)(k0 + kk2) * LD + n0 + nn2];
        }
        __syncthreads();
#pragma unroll
        for (int kk = 0; kk < 16; ++kk) {
            float a[4], bb[4];
#pragma unroll
            for (int i = 0; i < 4; ++i) { a[i] = As[kk][ty * 4 + i]; bb[i] = Bs[kk][tx * 4 + i]; }
#pragma unroll
            for (int i = 0; i < 4; ++i)
#pragma unroll
                for (int j = 0; j < 4; ++j) acc[i][j] += a[i] * bb[j];
        }
        __syncthreads();
    }

#pragma unroll
    for (int i = 0; i < 4; ++i) {
        int mg = m0 + ty * 4 + i;
        float sc = (MODE == 2) ? gamma[mg] * rsqrtf(rvar[mg] + BN_EPS) : 1.f;
#pragma unroll
        for (int j = 0; j < 4; ++j)
            Cm[(long)mg * LD + n0 + tx * 4 + j] = acc[i][j] * sc;
    }
}

// ---------------- launch ----------------
extern "C" void kernel_launch(void* const* d_in, const int* in_sizes, int n_in,
                              void* d_out, int out_size)
{
    const float* x      = (const float*)d_in[0];
    const float* w_qkv  = (const float*)d_in[1];
    const float* w_proj = (const float*)d_in[2];
    const float* gamma  = (const float*)d_in[3];
    const float* beta   = (const float*)d_in[4];
    const float* rmean  = (const float*)d_in[5];
    const float* rvar   = (const float*)d_in[6];
    float* out = (float*)d_out;

    cudaFuncSetAttribute((const void*)mma_big<0>, cudaFuncAttributeMaxDynamicSharedMemorySize, SMEM_MMA);
    cudaFuncSetAttribute((const void*)mma_big<1>, cudaFuncAttributeMaxDynamicSharedMemorySize, SMEM_MMA);
    cudaFuncSetAttribute((const void*)mma_ctx,    cudaFuncAttributeMaxDynamicSharedMemorySize, SMEM_MMA);

    // 0) X -> xt (transposed) and xn (straight) bf16 hi/lo
    transpose_split<<<dim3(NNS / 32, CC / 32, BB), dim3(32, 8)>>>(x);

    // 1) g_k = Wk @ X   (Wk = w_qkv rows [256,512); fp32 A converted in-loop, as in R8)
    mma_big<0><<<dim3(NNS / 128, 2, BB), 256, SMEM_MMA>>>(w_qkv + CC * CC, nullptr,
                                                          nullptr, nullptr, nullptr, nullptr);

    // 2) softmax stats + E = exp(K-m) bf16 hi/lo
    rowstats_econv<<<BB * CC, 256>>>();

    // 3) split-K partials: E @ X^T -> g_Spp  (pure cp.async loaders)
    mma_ctx<<<dim3(4, SPLITS, BB), 256, SMEM_MMA>>>();

    // 3b) reduce partials -> g_Sp
    reduce_sp<<<512, 256>>>();

    // 4) g_A0 = Wproj @ Wv
    sgemm_small<0><<<dim3(4, 4, 1), 256>>>(w_proj, w_qkv + 2 * CC * CC, nullptr, nullptr);

    // 5) g_U[b] = diag(1/s)-weighted S'^T @ Wq
    sgemm_small<1><<<dim3(4, 4, BB), 256>>>(w_qkv, nullptr, nullptr, nullptr);

    // 6) g_P2[b] (fp32) = diag(inv) * (A0 @ U[b])
    sgemm_small<2><<<dim3(4, 4, BB), 256>>>(nullptr, nullptr, gamma, rvar);

    // 7) out = relu(P2 @ X + (beta - mean*inv))
    mma_big<1><<<dim3(NNS / 128, 2, BB), 256, SMEM_MMA>>>(nullptr, out,
                                                          gamma, beta, rmean, rvar);
}

// round 12
// speedup vs baseline: 2.0445x; 1.0488x over previous
#include <cuda_runtime.h>
#include <cuda_bf16.h>
#include <cstdint>

#define BB 8
#define CC 256
#define NNS 16384
#define BN_EPS 1e-5f
#define SPLITS 16

// ---------------- scratch (static device globals; no allocation allowed) ----------------
__device__ __align__(16) float g_k[(size_t)BB * CC * NNS];              // fp32 K = Wk @ X
__device__ __align__(16) float g_m[BB * CC];                            // per-row max
__device__ __align__(16) float g_s[BB * CC];                            // per-row 1/sum(exp)
__device__ __align__(16) float g_Spp[(size_t)SPLITS * BB * CC * CC];    // split-K partials
__device__ __align__(16) float g_Sp[BB * CC * CC];                      // S' reduced
__device__ __align__(16) float g_A0[CC * CC];                           // Wproj @ Wv
__device__ __align__(16) float g_U[BB * CC * CC];                       // weighted S'^T @ Wq
__device__ __align__(16) float g_P2[BB * CC * CC];                      // diag(inv) * A0 @ U (fp32)
__device__ __align__(16) __nv_bfloat16 g_xt_h[(size_t)BB * NNS * CC];   // X^T hi [b][n][c]
__device__ __align__(16) __nv_bfloat16 g_xt_l[(size_t)BB * NNS * CC];   // X^T lo
__device__ __align__(16) __nv_bfloat16 g_xn_h[(size_t)BB * CC * NNS];   // X   hi [b][c][n]
__device__ __align__(16) __nv_bfloat16 g_xn_l[(size_t)BB * CC * NNS];   // X   lo
__device__ __align__(16) __nv_bfloat16 g_e_h[(size_t)BB * CC * NNS];    // exp(K-m) hi [b][o][n]
__device__ __align__(16) __nv_bfloat16 g_e_l[(size_t)BB * CC * NNS];    // exp(K-m) lo

// ================= helpers (base-sm_103-safe PTX only) =================
__device__ __forceinline__ uint32_t smem_to_u32(const void* p) {
    uint32_t a;
    asm("{ .reg .u64 t; cvta.to.shared.u64 t, %1; cvt.u32.u64 %0, t; }" : "=r"(a) : "l"(p));
    return a;
}
__device__ __forceinline__ void ldsm4(uint32_t* r, uint32_t addr) {
    asm volatile("ldmatrix.sync.aligned.m8n8.x4.shared.b16 {%0,%1,%2,%3}, [%4];"
                 : "=r"(r[0]), "=r"(r[1]), "=r"(r[2]), "=r"(r[3]) : "r"(addr));
}
__device__ __forceinline__ void mma_bf16(float* c, const uint32_t* a, const uint32_t* b) {
    asm volatile("mma.sync.aligned.m16n8k16.row.col.f32.bf16.bf16.f32 "
                 "{%0,%1,%2,%3}, {%4,%5,%6,%7}, {%8,%9}, {%0,%1,%2,%3};"
                 : "+f"(c[0]), "+f"(c[1]), "+f"(c[2]), "+f"(c[3])
                 : "r"(a[0]), "r"(a[1]), "r"(a[2]), "r"(a[3]), "r"(b[0]), "r"(b[1]));
}
__device__ __forceinline__ void cp_async16(uint32_t dst, const void* src) {
    asm volatile("cp.async.cg.shared.global [%0], [%1], 16;" :: "r"(dst), "l"(src));
}
#define CP_COMMIT() asm volatile("cp.async.commit_group;" ::: "memory")
#define CP_WAIT0()  asm volatile("cp.async.wait_group 0;" ::: "memory")

__device__ __forceinline__ uint32_t pack2(float a, float b) {
    union { __nv_bfloat162 v; uint32_t u; } cv;
    cv.v = __floats2bfloat162_rn(a, b);
    return cv.u;
}
__device__ __forceinline__ float hi_of(float a) {
    return __bfloat162float(__float2bfloat16(a));
}

// ---------------- SMEM layout: padded rows of 40 b16 (80 B) -> conflict-free ldmatrix ----------------
#define RSB 80
#define OFF_AH 0
#define OFF_AL 10240
#define OFF_BH 20480
#define OFF_BL 30720
#define STAGE  40960
#define SMEM_MMA (2 * STAGE)            // 81920, double buffered

// ---------------- X transpose + bf16 hi/lo split (both layouts) ----------------
__global__ void __launch_bounds__(256)
transpose_split(const float* __restrict__ x)
{
    __shared__ float sm[32][33];
    const int b = blockIdx.z, c0 = blockIdx.y * 32, n0 = blockIdx.x * 32;
    const int tx = threadIdx.x, ty = threadIdx.y;   // 32 x 8
    const float* xs = x + ((size_t)b * CC + c0) * NNS + n0;
    float v[4];
#pragma unroll
    for (int i = 0; i < 4; ++i) {
        v[i] = xs[(size_t)(ty + i * 8) * NNS + tx];
        sm[ty + i * 8][tx] = v[i];
    }
    // straight layout [c][n] bf16 hi/lo (for ctx B operand)
    const size_t nbase = ((size_t)b * CC + c0) * NNS + n0;
#pragma unroll
    for (int i = 0; i < 4; ++i) {
        int c = ty + i * 8;
        __nv_bfloat16 h = __float2bfloat16(v[i]);
        g_xn_h[nbase + (size_t)c * NNS + tx] = h;
        g_xn_l[nbase + (size_t)c * NNS + tx] = __float2bfloat16(v[i] - __bfloat162float(h));
    }
    __syncthreads();
    // transposed layout [n][c] bf16 hi/lo (for big GEMM B operand)
    const size_t obase = ((size_t)b * NNS + n0) * CC + c0;
#pragma unroll
    for (int i = 0; i < 4; ++i) {
        int n = ty + i * 8;
        float f = sm[tx][n];
        __nv_bfloat16 h = __float2bfloat16(f);
        g_xt_h[obase + (size_t)n * CC + tx] = h;
        g_xt_l[obase + (size_t)n * CC + tx] = __float2bfloat16(f - __bfloat162float(h));
    }
}

// ---------------- big HMMA GEMM: D[b] = A(fp32, reg-pipelined split) @ Xt[b] ----------------
// MODE 0: A = Ap_ (Wk), D -> g_k.   MODE 1: A = g_P2[b], D -> outp with BN bias + ReLU.
template <int MODE>
__global__ void __launch_bounds__(256)
mma_big(const float* __restrict__ Ap_, float* __restrict__ outp,
        const float* __restrict__ gamma, const float* __restrict__ beta,
        const float* __restrict__ rmean, const float* __restrict__ rvar)
{
    extern __shared__ __align__(16) char smem[];
    const int tid = threadIdx.x, lid = tid & 31, wid = tid >> 5;
    const int wm = wid & 1, wn = wid >> 1;
    const int b = blockIdx.z, m0 = blockIdx.y * 128, n0 = blockIdx.x * 128;
    const float* A = ((MODE == 0) ? Ap_ : (g_P2 + (size_t)b * CC * CC)) + (size_t)m0 * CC;
    const __nv_bfloat16* bhg = g_xt_h + ((size_t)b * NNS + n0) * CC;
    const __nv_bfloat16* blg = g_xt_l + ((size_t)b * NNS + n0) * CC;
    const uint32_t sb = smem_to_u32(smem);

    float acc[4][4][4];
#pragma unroll
    for (int f = 0; f < 4; ++f)
#pragma unroll
        for (int j = 0; j < 4; ++j)
#pragma unroll
            for (int e = 0; e < 4; ++e) acc[f][j][e] = 0.f;

    float4 areg[4];                      // register staging for next A slice
    auto ldgA = [&](int ks) {            // fetch A 128x32 fp32 slice -> registers
#pragma unroll
        for (int i = 0; i < 4; ++i) {
            int idx = tid + i * 256;             // 0..1023 float4s
            int r = idx >> 3, q = idx & 7;
            areg[i] = *reinterpret_cast<const float4*>(A + ks * 32 + (size_t)r * CC + q * 4);
        }
    };
    auto stsA = [&](int st) {            // convert regs -> hi/lo bf16, store (R8-proven math)
        char* bp = smem + st * STAGE;
#pragma unroll
        for (int i = 0; i < 4; ++i) {
            int idx = tid + i * 256;
            int r = idx >> 3, q = idx & 7;
            float4 v = areg[i];
            uint32_t h01 = pack2(v.x, v.y), h23 = pack2(v.z, v.w);
            uint32_t l01 = pack2(v.x - hi_of(v.x), v.y - hi_of(v.y));
            uint32_t l23 = pack2(v.z - hi_of(v.z), v.w - hi_of(v.w));
            *reinterpret_cast<uint2*>(bp + OFF_AH + r * RSB + q * 8) = make_uint2(h01, h23);
            *reinterpret_cast<uint2*>(bp + OFF_AL + r * RSB + q * 8) = make_uint2(l01, l23);
        }
    };
    auto loadB = [&](int ks, int st) {   // B 128 n-rows x 32 c, direct bf16 copies via cp.async
        uint32_t dst = sb + st * STAGE;
#pragma unroll
        for (int i = 0; i < 2; ++i) {
            int idx = tid + i * 256;             // 0..511 16B chunks
            int r = idx >> 2, q = idx & 3;
            cp_async16(dst + OFF_BH + r * RSB + q * 16, bhg + (size_t)r * CC + ks * 32 + q * 8);
            cp_async16(dst + OFF_BL + r * RSB + q * 16, blg + (size_t)r * CC + ks * 32 + q * 8);
        }
    };
    auto compute = [&](int st) {
        const uint32_t s0 = sb + st * STAGE;
#pragma unroll
        for (int k16 = 0; k16 < 2; ++k16) {
            const int ko = k16 * 16;
            uint32_t ah[4][4], al[4][4], bhf[2][4], blf[2][4];
            const uint32_t acol = (uint32_t)(ko + ((lid >> 4) << 3)) << 1;
#pragma unroll
            for (int f = 0; f < 4; ++f) {
                uint32_t row = (uint32_t)(wm * 64 + f * 16 + (lid & 15));
                ldsm4(ah[f], s0 + OFF_AH + row * RSB + acol);
                ldsm4(al[f], s0 + OFF_AL + row * RSB + acol);
            }
            const uint32_t bcol = (uint32_t)(ko + (((lid >> 3) & 1) << 3)) << 1;
#pragma unroll
            for (int p = 0; p < 2; ++p) {
                uint32_t nr = (uint32_t)(wn * 32 + p * 16 + (lid & 7) + ((lid >> 4) << 3));
                ldsm4(bhf[p], s0 + OFF_BH + nr * RSB + bcol);
                ldsm4(blf[p], s0 + OFF_BL + nr * RSB + bcol);
            }
#pragma unroll
            for (int f = 0; f < 4; ++f)
#pragma unroll
                for (int j = 0; j < 4; ++j) {
                    const int p = j >> 1, h = j & 1;
                    uint32_t bh2[2] = {bhf[p][h * 2], bhf[p][h * 2 + 1]};
                    uint32_t bl2[2] = {blf[p][h * 2], blf[p][h * 2 + 1]};
                    mma_bf16(acc[f][j], ah[f], bh2);
                    mma_bf16(acc[f][j], ah[f], bl2);
                    mma_bf16(acc[f][j], al[f], bh2);
                }
        }
    };

    // prologue: stage 0 fully populated before loop
    loadB(0, 0); CP_COMMIT();
    ldgA(0);
    stsA(0);
    for (int s = 0; s < 8; ++s) {
        CP_WAIT0();                         // B(s) landed (committed last iter / prologue)
        __syncthreads();                    // A(s)+B(s) visible; all readers of buf (s+1)&1 done
        if (s < 7) {
            loadB(s + 1, (s + 1) & 1);      // async into other buffer
            CP_COMMIT();
            ldgA(s + 1);                    // LDG latency overlaps compute(s)
        }
        compute(s & 1);
        if (s < 7) stsA((s + 1) & 1);       // data already in regs; issue-only cost
    }

    // epilogue (R8 verbatim)
    float* outb = (MODE == 0 ? g_k : outp) + (size_t)b * CC * NNS;
    const int colb = n0 + wn * 32 + 2 * (lid & 3);
#pragma unroll
    for (int f = 0; f < 4; ++f) {
        const int r0 = m0 + wm * 64 + f * 16 + (lid >> 2);
        float bias0 = 0.f, bias1 = 0.f;
        if (MODE == 1) {
            float i0 = gamma[r0] * rsqrtf(rvar[r0] + BN_EPS);
            float i1 = gamma[r0 + 8] * rsqrtf(rvar[r0 + 8] + BN_EPS);
            bias0 = beta[r0] - rmean[r0] * i0;
            bias1 = beta[r0 + 8] - rmean[r0 + 8] * i1;
        }
#pragma unroll
        for (int j = 0; j < 4; ++j) {
            const int cc0 = colb + j * 8;
            float2 v0 = make_float2(acc[f][j][0], acc[f][j][1]);
            float2 v1 = make_float2(acc[f][j][2], acc[f][j][3]);
            if (MODE == 1) {
                v0.x = fmaxf(v0.x + bias0, 0.f); v0.y = fmaxf(v0.y + bias0, 0.f);
                v1.x = fmaxf(v1.x + bias1, 0.f); v1.y = fmaxf(v1.y + bias1, 0.f);
            }
            *reinterpret_cast<float2*>(outb + (size_t)r0 * NNS + cc0)       = v0;
            *reinterpret_cast<float2*>(outb + (size_t)(r0 + 8) * NNS + cc0) = v1;
        }
    }
}

// ---------------- ctx HMMA GEMM (R11 VERBATIM): S'_partial = E @ Xn^T over 1024 n ----------------
__global__ void __launch_bounds__(256)
mma_ctx()
{
    extern __shared__ __align__(16) char smem[];
    const int tid = threadIdx.x, lid = tid & 31, wid = tid >> 5;
    const int wm = wid & 1, wn = wid >> 1;
    const int o0 = (blockIdx.x >> 1) * 128, c0 = (blockIdx.x & 1) * 128;
    const int split = blockIdx.y, b = blockIdx.z;
    const uint32_t sb = smem_to_u32(smem);

    const size_t ko0 = (size_t)split * 1024;
    const __nv_bfloat16* ehg = g_e_h + ((size_t)b * CC + o0) * NNS + ko0;
    const __nv_bfloat16* elg = g_e_l + ((size_t)b * CC + o0) * NNS + ko0;
    const __nv_bfloat16* xhg = g_xn_h + ((size_t)b * CC + c0) * NNS + ko0;
    const __nv_bfloat16* xlg = g_xn_l + ((size_t)b * CC + c0) * NNS + ko0;

    float acc[4][4][4];
#pragma unroll
    for (int f = 0; f < 4; ++f)
#pragma unroll
        for (int j = 0; j < 4; ++j)
#pragma unroll
            for (int e = 0; e < 4; ++e) acc[f][j][e] = 0.f;

    auto loadT = [&](int ks, int st) {
        uint32_t dst = sb + st * STAGE;
#pragma unroll
        for (int i = 0; i < 2; ++i) {
            int idx = tid + i * 256;             // 0..511 16B chunks
            int r = idx >> 2, q = idx & 3;
            size_t so = (size_t)r * NNS + (size_t)ks * 32 + q * 8;
            cp_async16(dst + OFF_AH + r * RSB + q * 16, ehg + so);
            cp_async16(dst + OFF_AL + r * RSB + q * 16, elg + so);
            cp_async16(dst + OFF_BH + r * RSB + q * 16, xhg + so);
            cp_async16(dst + OFF_BL + r * RSB + q * 16, xlg + so);
        }
    };
    auto compute = [&](int st) {
        const uint32_t s0 = sb + st * STAGE;
#pragma unroll
        for (int k16 = 0; k16 < 2; ++k16) {
            const int ko = k16 * 16;
            uint32_t ah[4][4], al[4][4], bhf[2][4], blf[2][4];
            const uint32_t acol = (uint32_t)(ko + ((lid >> 4) << 3)) << 1;
#pragma unroll
            for (int f = 0; f < 4; ++f) {
                uint32_t row = (uint32_t)(wm * 64 + f * 16 + (lid & 15));
                ldsm4(ah[f], s0 + OFF_AH + row * RSB + acol);
                ldsm4(al[f], s0 + OFF_AL + row * RSB + acol);
            }
            const uint32_t bcol = (uint32_t)(ko + (((lid >> 3) & 1) << 3)) << 1;
#pragma unroll
            for (int p = 0; p < 2; ++p) {
                uint32_t nr = (uint32_t)(wn * 32 + p * 16 + (lid & 7) + ((lid >> 4) << 3));
                ldsm4(bhf[p], s0 + OFF_BH + nr * RSB + bcol);
                ldsm4(blf[p], s0 + OFF_BL + nr * RSB + bcol);
            }
#pragma unroll
            for (int f = 0; f < 4; ++f)
#pragma unroll
                for (int j = 0; j < 4; ++j) {
                    const int p = j >> 1, h = j & 1;
                    uint32_t bh2[2] = {bhf[p][h * 2], bhf[p][h * 2 + 1]};
                    uint32_t bl2[2] = {blf[p][h * 2], blf[p][h * 2 + 1]};
                    mma_bf16(acc[f][j], ah[f], bh2);
                    mma_bf16(acc[f][j], ah[f], bl2);
                    mma_bf16(acc[f][j], al[f], bh2);
                }
        }
    };

    loadT(0, 0); CP_COMMIT();
    for (int s = 0; s < 32; ++s) {
        CP_WAIT0();
        __syncthreads();
        if (s < 31) { loadT(s + 1, (s + 1) & 1); CP_COMMIT(); }
        compute(s & 1);
    }

    float* dstb = g_Spp + ((size_t)split * BB + b) * CC * CC;
    const int colb = c0 + wn * 32 + 2 * (lid & 3);
#pragma unroll
    for (int f = 0; f < 4; ++f) {
        const int r0 = o0 + wm * 64 + f * 16 + (lid >> 2);
#pragma unroll
        for (int j = 0; j < 4; ++j) {
            const int cc0 = colb + j * 8;
            *reinterpret_cast<float2*>(dstb + (size_t)r0 * CC + cc0) =
                make_float2(acc[f][j][0], acc[f][j][1]);
            *reinterpret_cast<float2*>(dstb + (size_t)(r0 + 8) * CC + cc0) =
                make_float2(acc[f][j][2], acc[f][j][3]);
        }
    }
}

// ---------------- per-row max + 1/sum(exp) + E=exp(K-m) bf16 hi/lo writeback ----------------
__global__ void __launch_bounds__(256)
rowstats_econv()
{
    const size_t row = blockIdx.x;  // 0..2047 == b*256 + o
    const float4* kr = reinterpret_cast<const float4*>(g_k) + row * (NNS / 4);
    const int t = threadIdx.x;

    float4 v[16];
    float mx = -3.402823466e38f;
#pragma unroll
    for (int i = 0; i < 16; ++i) {
        v[i] = kr[t + (i << 8)];
        mx = fmaxf(mx, fmaxf(fmaxf(v[i].x, v[i].y), fmaxf(v[i].z, v[i].w)));
    }
    __shared__ float red[8];
    __shared__ float bmax;
#pragma unroll
    for (int o = 16; o; o >>= 1) mx = fmaxf(mx, __shfl_xor_sync(0xffffffffu, mx, o));
    if ((t & 31) == 0) red[t >> 5] = mx;
    __syncthreads();
    if (t < 32) {
        float x2 = (t < 8) ? red[t] : -3.402823466e38f;
#pragma unroll
        for (int o = 4; o; o >>= 1) x2 = fmaxf(x2, __shfl_xor_sync(0xffffffffu, x2, o));
        if (t == 0) bmax = x2;
    }
    __syncthreads();
    const float m = bmax;

    uint2* eh = reinterpret_cast<uint2*>(g_e_h + row * NNS);
    uint2* el = reinterpret_cast<uint2*>(g_e_l + row * NNS);
    float s = 0.f;
#pragma unroll
    for (int i = 0; i < 16; ++i) {
        float ex = __expf(v[i].x - m), ey = __expf(v[i].y - m);
        float ez = __expf(v[i].z - m), ew = __expf(v[i].w - m);
        s += ex + ey + ez + ew;
        const int q = t + (i << 8);                 // float4 index within row
        eh[q] = make_uint2(pack2(ex, ey), pack2(ez, ew));
        el[q] = make_uint2(pack2(ex - hi_of(ex), ey - hi_of(ey)),
                           pack2(ez - hi_of(ez), ew - hi_of(ew)));
    }
#pragma unroll
    for (int o = 16; o; o >>= 1) s += __shfl_xor_sync(0xffffffffu, s, o);
    if ((t & 31) == 0) red[t >> 5] = s;
    __syncthreads();
    if (t < 32) {
        float x2 = (t < 8) ? red[t] : 0.f;
#pragma unroll
        for (int o = 4; o; o >>= 1) x2 += __shfl_xor_sync(0xffffffffu, x2, o);
        if (t == 0) { g_m[row] = m; g_s[row] = 1.0f / x2; }
    }
}

// ---------------- reduce the 16 split partials into g_Sp ----------------
__global__ void __launch_bounds__(256)
reduce_sp()
{
    const int idx = blockIdx.x * 256 + threadIdx.x;
    const float4* src = reinterpret_cast<const float4*>(g_Spp);
    float4 a = make_float4(0.f, 0.f, 0.f, 0.f);
#pragma unroll
    for (int s = 0; s < SPLITS; ++s) {
        float4 v = src[(long)s * (BB * CC * CC / 4) + idx];
        a.x += v.x; a.y += v.y; a.z += v.z; a.w += v.w;
    }
    reinterpret_cast<float4*>(g_Sp)[idx] = a;
}

// ---------------- small 256^3 GEMMs (R8 VERBATIM, fp32 P2 output) ----------------
template <int MODE>
__global__ void __launch_bounds__(256)
sgemm_small(const float* __restrict__ in0, const float* __restrict__ in1,
            const float* __restrict__ gamma, const float* __restrict__ rvar)
{
    const int LD = CC;
    const int b = blockIdx.z;
    const float* A = (MODE == 0) ? in0 : (MODE == 1) ? (g_Sp + (long)b * CC * CC) : g_A0;
    const float* Bm = (MODE == 0) ? in1 : (MODE == 1) ? in0 : (g_U + (long)b * CC * CC);
    float* Cm = (MODE == 0) ? g_A0 : (MODE == 1) ? (g_U + (long)b * CC * CC)
                                                  : (g_P2 + (long)b * CC * CC);
    const float* ks = (MODE == 1) ? (g_s + (long)b * CC) : nullptr;
    const int m0 = blockIdx.y * 64, n0 = blockIdx.x * 64;

    __shared__ float As[16][65];
    __shared__ float Bs[16][65];

    const int tid = threadIdx.x;
    const int tx = tid & 15, ty = tid >> 4;
    float acc[4][4] = {};

    for (int k0 = 0; k0 < CC; k0 += 16) {
#pragma unroll
        for (int p = 0; p < 4; ++p) {
            int idx = tid + p * 256;
            if (MODE == 1) {
                int kk = idx >> 6, mm = idx & 63;
                As[kk][mm] = A[(long)(k0 + kk) * LD + m0 + mm] * ks[k0 + kk];
            } else {
                int mm = idx >> 4, kk = idx & 15;
                As[kk][mm] = A[(long)(m0 + mm) * LD + k0 + kk];
            }
            int kk2 = idx >> 6, nn2 = idx & 63;
            Bs[kk2][nn2] = Bm[(long)(k0 + kk2) * LD + n0 + nn2];
        }
        __syncthreads();
#pragma unroll
        for (int kk = 0; kk < 16; ++kk) {
            float a[4], bb[4];
#pragma unroll
            for (int i = 0; i < 4; ++i) { a[i] = As[kk][ty * 4 + i]; bb[i] = Bs[kk][tx * 4 + i]; }
#pragma unroll
            for (int i = 0; i < 4; ++i)
#pragma unroll
                for (int j = 0; j < 4; ++j) acc[i][j] += a[i] * bb[j];
        }
        __syncthreads();
    }

#pragma unroll
    for (int i = 0; i < 4; ++i) {
        int mg = m0 + ty * 4 + i;
        float sc = (MODE == 2) ? gamma[mg] * rsqrtf(rvar[mg] + BN_EPS) : 1.f;
#pragma unroll
        for (int j = 0; j < 4; ++j)
            Cm[(long)mg * LD + n0 + tx * 4 + j] = acc[i][j] * sc;
    }
}

// ---------------- launch ----------------
extern "C" void kernel_launch(void* const* d_in, const int* in_sizes, int n_in,
                              void* d_out, int out_size)
{
    const float* x      = (const float*)d_in[0];
    const float* w_qkv  = (const float*)d_in[1];
    const float* w_proj = (const float*)d_in[2];
    const float* gamma  = (const float*)d_in[3];
    const float* beta   = (const float*)d_in[4];
    const float* rmean  = (const float*)d_in[5];
    const float* rvar   = (const float*)d_in[6];
    float* out = (float*)d_out;

    cudaFuncSetAttribute((const void*)mma_big<0>, cudaFuncAttributeMaxDynamicSharedMemorySize, SMEM_MMA);
    cudaFuncSetAttribute((const void*)mma_big<1>, cudaFuncAttributeMaxDynamicSharedMemorySize, SMEM_MMA);
    cudaFuncSetAttribute((const void*)mma_ctx,    cudaFuncAttributeMaxDynamicSharedMemorySize, SMEM_MMA);

    // 0) X -> xt (transposed) and xn (straight) bf16 hi/lo
    transpose_split<<<dim3(NNS / 32, CC / 32, BB), dim3(32, 8)>>>(x);

    // 1) g_k = Wk @ X   (Wk = w_qkv rows [256,512); fp32 A reg-pipelined in-loop)
    mma_big<0><<<dim3(NNS / 128, 2, BB), 256, SMEM_MMA>>>(w_qkv + CC * CC, nullptr,
                                                          nullptr, nullptr, nullptr, nullptr);

    // 2) softmax stats + E = exp(K-m) bf16 hi/lo
    rowstats_econv<<<BB * CC, 256>>>();

    // 3) split-K partials: E @ X^T -> g_Spp  (pure cp.async loaders)
    mma_ctx<<<dim3(4, SPLITS, BB), 256, SMEM_MMA>>>();

    // 3b) reduce partials -> g_Sp
    reduce_sp<<<512, 256>>>();

    // 4) g_A0 = Wproj @ Wv
    sgemm_small<0><<<dim3(4, 4, 1), 256>>>(w_proj, w_qkv + 2 * CC * CC, nullptr, nullptr);

    // 5) g_U[b] = diag(1/s)-weighted S'^T @ Wq
    sgemm_small<1><<<dim3(4, 4, BB), 256>>>(w_qkv, nullptr, nullptr, nullptr);

    // 6) g_P2[b] (fp32) = diag(inv) * (A0 @ U[b])
    sgemm_small<2><<<dim3(4, 4, BB), 256>>>(nullptr, nullptr, gamma, rvar);

    // 7) out = relu(P2 @ X + (beta - mean*inv))
    mma_big<1><<<dim3(NNS / 128, 2, BB), 256, SMEM_MMA>>>(nullptr, out,
                                                          gamma, beta, rmean, rvar);
}